// round 14
// baseline (speedup 1.0000x reference)
#include <cuda_runtime.h>
#include <math.h>

static constexpr int B    = 16;
static constexpr int C    = 64;
static constexpr int HW   = 256 * 256;   // 65536
static constexpr int HW4  = HW / 4;      // 16384
static constexpr int PB   = 64;          // pool blocks per batch (HW4/256)
static constexpr int NRM  = (B * 3 * HW4) / 256;  // 3072 norm blocks

// Per-block partial sums: [B][PB][8] (7 used: sum/sumsq x3 channels, cnt).
// Every slot overwritten every launch -> no zeroing, no atomics in pool.
__device__ float    g_part[B * PB * 8];
__device__ float    g_mean[B * 3];
__device__ float    g_istd[B * 3];
__device__ unsigned g_gate;   // -> 16 when stats ready; reset each launch
__device__ unsigned g_done;   // norm-block completion counter; reset each launch

// ---------------------------------------------------------------------------
// K1: channel pool (max/mean/min over C) + masked per-block partial sums.
// EXACT R6/R12 body — profiled 43.3-44.1us / 6.4 TB/s = compulsory traffic
// (HBM floor). DO NOT EDIT THIS BODY:
//  - explicit front-batched loads regressed ~30% (R7, L1tex-queue contention)
//  - fused stats tail / ticket atomics regressed ~60% (R9, epilogue pressure)
// ---------------------------------------------------------------------------
__global__ __launch_bounds__(256) void pool_kernel(const float* __restrict__ x,
                                                   const int*   __restrict__ mask,
                                                   float*       __restrict__ out) {
    const int b   = blockIdx.y;
    const int idx = blockIdx.x * blockDim.x + threadIdx.x;  // float4 index in HW4

    const float4* xb = reinterpret_cast<const float4*>(x) + (size_t)b * C * HW4 + idx;

    float4 mx = make_float4(-INFINITY, -INFINITY, -INFINITY, -INFINITY);
    float4 mn = make_float4( INFINITY,  INFINITY,  INFINITY,  INFINITY);
    float4 sm = make_float4(0.f, 0.f, 0.f, 0.f);

#pragma unroll 8
    for (int c = 0; c < C; c++) {
        float4 t = xb[(size_t)c * HW4];
        mx.x = fmaxf(mx.x, t.x); mx.y = fmaxf(mx.y, t.y);
        mx.z = fmaxf(mx.z, t.z); mx.w = fmaxf(mx.w, t.w);
        mn.x = fminf(mn.x, t.x); mn.y = fminf(mn.y, t.y);
        mn.z = fminf(mn.z, t.z); mn.w = fminf(mn.w, t.w);
        sm.x += t.x; sm.y += t.y; sm.z += t.z; sm.w += t.w;
    }
    const float inv = 1.0f / (float)C;
    float4 me = make_float4(sm.x * inv, sm.y * inv, sm.z * inv, sm.w * inv);

    // Write pooled channels into out (scratch): [B, 3, HW] — stays in L2.
    float4* ob = reinterpret_cast<float4*>(out) + (size_t)b * 3 * HW4 + idx;
    ob[0]       = mx;
    ob[HW4]     = me;
    ob[2 * HW4] = mn;

    // Masked partial sums for this thread's 4 pixels.
    int4 mi = reinterpret_cast<const int4*>(mask)[b * HW4 + idx];
    float m0 = (mi.x == 1) ? 1.f : 0.f;
    float m1 = (mi.y == 1) ? 1.f : 0.f;
    float m2 = (mi.z == 1) ? 1.f : 0.f;
    float m3 = (mi.w == 1) ? 1.f : 0.f;

    float r[7];
    r[0] = mx.x * m0 + mx.y * m1 + mx.z * m2 + mx.w * m3;
    r[1] = mx.x * mx.x * m0 + mx.y * mx.y * m1 + mx.z * mx.z * m2 + mx.w * mx.w * m3;
    r[2] = me.x * m0 + me.y * m1 + me.z * m2 + me.w * m3;
    r[3] = me.x * me.x * m0 + me.y * me.y * m1 + me.z * me.z * m2 + me.w * me.w * m3;
    r[4] = mn.x * m0 + mn.y * m1 + mn.z * m2 + mn.w * m3;
    r[5] = mn.x * mn.x * m0 + mn.y * mn.y * m1 + mn.z * mn.z * m2 + mn.w * mn.w * m3;
    r[6] = m0 + m1 + m2 + m3;

    // Warp reduce
#pragma unroll
    for (int off = 16; off > 0; off >>= 1) {
#pragma unroll
        for (int k = 0; k < 7; k++)
            r[k] += __shfl_down_sync(0xffffffffu, r[k], off);
    }

    __shared__ float sh[7][8];
    int lane = threadIdx.x & 31;
    int w    = threadIdx.x >> 5;
    if (lane == 0) {
#pragma unroll
        for (int k = 0; k < 7; k++) sh[k][w] = r[k];
    }
    __syncthreads();

    if (w == 0) {
#pragma unroll
        for (int k = 0; k < 7; k++) r[k] = (lane < 8) ? sh[k][lane] : 0.f;
#pragma unroll
        for (int off = 4; off > 0; off >>= 1) {
#pragma unroll
            for (int k = 0; k < 7; k++)
                r[k] += __shfl_down_sync(0xffffffffu, r[k], off);
        }
        if (lane == 0) {
            float* p = &g_part[(b * PB + blockIdx.x) * 8];
#pragma unroll
            for (int k = 0; k < 7; k++) p[k] = r[k];
        }
    }
}

// ---------------------------------------------------------------------------
// K2: fused stats + normalize (single launch, flag-gated).
// Blocks 0..15 first compute stats for batch == blockIdx.x (R12's proven
// shuffle reduce), publish via threadfence + g_gate. ALL blocks gate on
// g_gate==16 (producers are bids 0-15 => resident in wave 1 => no deadlock),
// then run the EXACT R5 norm body (1 float4/thread; do not batch loads —
// ILP variants regressed 3x in R6/R8). Last block resets counters so the
// kernel is graph-replay-safe with no zeroing launch.
// ---------------------------------------------------------------------------
__global__ __launch_bounds__(256) void norm_kernel(const int* __restrict__ mask,
                                                   float*     __restrict__ out) {
    // ---- stats production (blocks 0..15, warp 0 only) ----
    if (blockIdx.x < B && threadIdx.x < 32) {
        const int bb   = blockIdx.x;
        const int lane = threadIdx.x;

        double a[7];
        const float* p0 = &g_part[(bb * PB + lane) * 8];
        const float* p1 = &g_part[(bb * PB + lane + 32) * 8];
#pragma unroll
        for (int k = 0; k < 7; k++) a[k] = (double)p0[k] + (double)p1[k];
#pragma unroll
        for (int off = 16; off > 0; off >>= 1) {
#pragma unroll
            for (int k = 0; k < 7; k++)
                a[k] += __shfl_down_sync(0xffffffffu, a[k], off);
        }
        if (lane == 0) {
            double cnt = a[6];
#pragma unroll
            for (int ch = 0; ch < 3; ch++) {
                double s    = a[ch * 2];
                double ss   = a[ch * 2 + 1];
                double mean = s / cnt;
                double var  = (ss - s * s / cnt) / (cnt - 1.0);
                g_mean[bb * 3 + ch] = (float)mean;
                g_istd[bb * 3 + ch] = (float)(1.0 / sqrt(var));
            }
            __threadfence();
            atomicAdd(&g_gate, 1u);
        }
    }

    // ---- gate: wait until all 16 batches' stats are published ----
    if (threadIdx.x == 0) {
        while (*(volatile unsigned*)&g_gate < (unsigned)B) { __nanosleep(64); }
    }
    __syncthreads();
    __threadfence();   // order stats reads after the observed flag

    // ---- EXACT R5 norm body ----
    int e4  = blockIdx.x * blockDim.x + threadIdx.x;   // float4 index in B*3*HW4
    int b3  = e4 >> 14;            // / HW4
    int hw4 = e4 & (HW4 - 1);
    int b   = b3 / 3;

    float mean = g_mean[b3];
    float is   = g_istd[b3];

    float4 v  = reinterpret_cast<float4*>(out)[e4];
    int4   mi = reinterpret_cast<const int4*>(mask)[b * HW4 + hw4];

    v.x = (mi.x == 1) ? (v.x - mean) * is : 0.f;
    v.y = (mi.y == 1) ? (v.y - mean) * is : 0.f;
    v.z = (mi.z == 1) ? (v.z - mean) * is : 0.f;
    v.w = (mi.w == 1) ? (v.w - mean) * is : 0.f;

    reinterpret_cast<float4*>(out)[e4] = v;

    // ---- replay-safe reset: last block to finish clears the counters.
    // Every block increments g_done only AFTER passing the gate, so when the
    // count hits NRM all blocks are past it -> safe to clear g_gate. ----
    if (threadIdx.x == 0) {
        unsigned d = atomicAdd(&g_done, 1u);
        if (d == (unsigned)(NRM - 1)) {
            g_gate = 0u;
            g_done = 0u;
            __threadfence();
        }
    }
}

// ---------------------------------------------------------------------------
extern "C" void kernel_launch(void* const* d_in, const int* in_sizes, int n_in,
                              void* d_out, int out_size) {
    const float* x    = (const float*)d_in[0];
    const int*   mask = (const int*)d_in[1];
    float*       out  = (float*)d_out;

    dim3 g1(PB, B);
    pool_kernel<<<g1, 256>>>(x, mask, out);

    norm_kernel<<<NRM, 256>>>(mask, out);
}

// round 15
// speedup vs baseline: 1.1554x; 1.1554x over previous
#include <cuda_runtime.h>
#include <math.h>

static constexpr int B   = 16;
static constexpr int C   = 64;
static constexpr int HW  = 256 * 256;   // 65536
static constexpr int HW4 = HW / 4;      // 16384

// Per-batch/channel accumulators (double: protects the sumsq - sum^2/cnt
// cancellation for unbiased variance across ~32K masked pixels).
__device__ double g_sum[B * 3];
__device__ double g_sumsq[B * 3];
__device__ double g_cnt[B];
__device__ float  g_mean[B * 3];
__device__ float  g_istd[B * 3];

// ---------------------------------------------------------------------------
// K0: reset accumulators (must run every graph replay).  [R5-exact]
// ---------------------------------------------------------------------------
__global__ void zero_kernel() {
    int t = threadIdx.x;
    if (t < B * 3) { g_sum[t] = 0.0; g_sumsq[t] = 0.0; }
    if (t < B)     { g_cnt[t] = 0.0; }
}

// ---------------------------------------------------------------------------
// K1: channel pool (max/mean/min over C) + masked partial sums per batch.
// [R5-exact body — profiled 43.3-44.1us / 6.4 TB/s = compulsory traffic =
//  HBM floor. DO NOT EDIT: front-batched loads (R7), fused stats tails (R9),
//  and gates (R14) all regressed 30-60%.]
// ---------------------------------------------------------------------------
__global__ __launch_bounds__(256) void pool_kernel(const float* __restrict__ x,
                                                   const int*   __restrict__ mask,
                                                   float*       __restrict__ out) {
    const int b   = blockIdx.y;
    const int idx = blockIdx.x * blockDim.x + threadIdx.x;  // float4 index in HW4

    const float4* xb = reinterpret_cast<const float4*>(x) + (size_t)b * C * HW4 + idx;

    float4 mx = make_float4(-INFINITY, -INFINITY, -INFINITY, -INFINITY);
    float4 mn = make_float4( INFINITY,  INFINITY,  INFINITY,  INFINITY);
    float4 sm = make_float4(0.f, 0.f, 0.f, 0.f);

#pragma unroll 8
    for (int c = 0; c < C; c++) {
        float4 t = xb[(size_t)c * HW4];
        mx.x = fmaxf(mx.x, t.x); mx.y = fmaxf(mx.y, t.y);
        mx.z = fmaxf(mx.z, t.z); mx.w = fmaxf(mx.w, t.w);
        mn.x = fminf(mn.x, t.x); mn.y = fminf(mn.y, t.y);
        mn.z = fminf(mn.z, t.z); mn.w = fminf(mn.w, t.w);
        sm.x += t.x; sm.y += t.y; sm.z += t.z; sm.w += t.w;
    }
    const float inv = 1.0f / (float)C;
    float4 me = make_float4(sm.x * inv, sm.y * inv, sm.z * inv, sm.w * inv);

    // Write pooled channels into out (scratch): [B, 3, HW] — stays in L2.
    float4* ob = reinterpret_cast<float4*>(out) + (size_t)b * 3 * HW4 + idx;
    ob[0]       = mx;
    ob[HW4]     = me;
    ob[2 * HW4] = mn;

    // Masked partial sums for this thread's 4 pixels.
    int4 mi = reinterpret_cast<const int4*>(mask)[b * HW4 + idx];
    float m0 = (mi.x == 1) ? 1.f : 0.f;
    float m1 = (mi.y == 1) ? 1.f : 0.f;
    float m2 = (mi.z == 1) ? 1.f : 0.f;
    float m3 = (mi.w == 1) ? 1.f : 0.f;

    float r[7];
    r[0] = mx.x * m0 + mx.y * m1 + mx.z * m2 + mx.w * m3;
    r[1] = mx.x * mx.x * m0 + mx.y * mx.y * m1 + mx.z * mx.z * m2 + mx.w * mx.w * m3;
    r[2] = me.x * m0 + me.y * m1 + me.z * m2 + me.w * m3;
    r[3] = me.x * me.x * m0 + me.y * me.y * m1 + me.z * me.z * m2 + me.w * me.w * m3;
    r[4] = mn.x * m0 + mn.y * m1 + mn.z * m2 + mn.w * m3;
    r[5] = mn.x * mn.x * m0 + mn.y * mn.y * m1 + mn.z * mn.z * m2 + mn.w * mn.w * m3;
    r[6] = m0 + m1 + m2 + m3;

    // Warp reduce
#pragma unroll
    for (int off = 16; off > 0; off >>= 1) {
#pragma unroll
        for (int k = 0; k < 7; k++)
            r[k] += __shfl_down_sync(0xffffffffu, r[k], off);
    }

    __shared__ float sh[7][8];
    int lane = threadIdx.x & 31;
    int w    = threadIdx.x >> 5;
    if (lane == 0) {
#pragma unroll
        for (int k = 0; k < 7; k++) sh[k][w] = r[k];
    }
    __syncthreads();

    if (w == 0) {
#pragma unroll
        for (int k = 0; k < 7; k++) r[k] = (lane < 8) ? sh[k][lane] : 0.f;
#pragma unroll
        for (int off = 4; off > 0; off >>= 1) {
#pragma unroll
            for (int k = 0; k < 7; k++)
                r[k] += __shfl_down_sync(0xffffffffu, r[k], off);
        }
        if (lane == 0) {
            atomicAdd(&g_sum[b * 3 + 0],   (double)r[0]);
            atomicAdd(&g_sumsq[b * 3 + 0], (double)r[1]);
            atomicAdd(&g_sum[b * 3 + 1],   (double)r[2]);
            atomicAdd(&g_sumsq[b * 3 + 1], (double)r[3]);
            atomicAdd(&g_sum[b * 3 + 2],   (double)r[4]);
            atomicAdd(&g_sumsq[b * 3 + 2], (double)r[5]);
            atomicAdd(&g_cnt[b],           (double)r[6]);
        }
    }
}

// ---------------------------------------------------------------------------
// K2: finalize mean / 1/std (unbiased variance).  [R5-exact]
// ---------------------------------------------------------------------------
__global__ void stats_kernel() {
    int t = threadIdx.x;
    if (t < B * 3) {
        double cnt  = g_cnt[t / 3];
        double s    = g_sum[t];
        double ss   = g_sumsq[t];
        double mean = s / cnt;
        double var  = (ss - s * s / cnt) / (cnt - 1.0);
        g_mean[t] = (float)mean;
        g_istd[t] = (float)(1.0 / sqrt(var));
    }
}

// ---------------------------------------------------------------------------
// K3: normalize in place: out = ((xc - mean) / std) * (mask==1).
// ONLY change vs the proven R5 body: 2 float4 per thread via a natural
// unrolled loop (ptxas schedules loads — NOT hand-front-batched; the
// MLP_p1=8 variants regressed 3x in R6/R8). Block covers 512 consecutive
// float4 -> b3 uniform per block (HW4 % 512 == 0). MLP_p1~4 = benign regime.
// ---------------------------------------------------------------------------
__global__ __launch_bounds__(256) void norm_kernel(const int* __restrict__ mask,
                                                   float*     __restrict__ out) {
    const int base = blockIdx.x * 512 + threadIdx.x;  // float4 index
    const int b3   = base >> 14;                       // uniform per block
    const int b    = b3 / 3;

    const float mean = g_mean[b3];
    const float is   = g_istd[b3];

    float4*     o4 = reinterpret_cast<float4*>(out);
    const int4* m4 = reinterpret_cast<const int4*>(mask);

#pragma unroll 2
    for (int j = 0; j < 2; j++) {
        int e4  = base + j * 256;
        int hw4 = e4 & (HW4 - 1);

        float4 v  = o4[e4];
        int4   mi = m4[b * HW4 + hw4];

        v.x = (mi.x == 1) ? (v.x - mean) * is : 0.f;
        v.y = (mi.y == 1) ? (v.y - mean) * is : 0.f;
        v.z = (mi.z == 1) ? (v.z - mean) * is : 0.f;
        v.w = (mi.w == 1) ? (v.w - mean) * is : 0.f;

        o4[e4] = v;
    }
}

// ---------------------------------------------------------------------------
extern "C" void kernel_launch(void* const* d_in, const int* in_sizes, int n_in,
                              void* d_out, int out_size) {
    const float* x    = (const float*)d_in[0];
    const int*   mask = (const int*)d_in[1];
    float*       out  = (float*)d_out;

    zero_kernel<<<1, 64>>>();

    dim3 g1(HW4 / 256, B);
    pool_kernel<<<g1, 256>>>(x, mask, out);

    stats_kernel<<<1, 64>>>();

    norm_kernel<<<(B * 3 * HW4) / 512, 256>>>(mask, out);
}